// round 17
// baseline (speedup 1.0000x reference)
#include <cuda_runtime.h>
#include <cuda_bf16.h>
#include <cstdint>

// Problem constants
#define B_   64
#define L_   4096
#define KD_  128
#define H_   4
#define OUT_ 256

#define CHUNKS 16                // L-chunks per batch (pass 1)
#define WARPS  4                 // warps per block in pass 1 (128 threads)
#define ROWS_PER_WARP (L_ / CHUNKS / WARPS)   // 64 rows per warp
#define NBLK1 (B_ * CHUNKS)      // 1024

// Deterministic scratch (no device allocation allowed)
__device__ float g_pacc[NBLK1][KD_ * H_];   // 1024 x 512 f32 = 2 MB
__device__ float g_pZ[NBLK1][H_];
__device__ float g_pooled[B_][KD_ * H_];    // normalized pooled vectors
__device__ int   g_cnt[B_];                 // BSS-zeroed; each run restores 0

__device__ __forceinline__ float warp_sum32(float v) {
#pragma unroll
    for (int off = 16; off >= 1; off >>= 1)
        v += __shfl_xor_sync(0xffffffffu, v, off);
    return v;
}

__device__ __forceinline__ uint32_t smem_u32(const void* p) {
    uint32_t a;
    asm("{ .reg .u64 t; cvta.to.shared.u64 t, %1; cvt.u32.u64 %0, t; }"
        : "=r"(a) : "l"(p));
    return a;
}

// Volatile LDS.128: guaranteed in-loop (prevents hoisting q back into regs).
__device__ __forceinline__ float4 lds128v(uint32_t addr) {
    float4 r;
    asm volatile("ld.shared.v4.f32 {%0,%1,%2,%3}, [%4];"
                 : "=f"(r.x), "=f"(r.y), "=f"(r.z), "=f"(r.w) : "r"(addr));
    return r;
}

// 8-value butterfly transpose-reduce. In: wv[0..7] per lane. Out: return on
// lane l == full 32-lane sum of value (l & 7). (R10/R13-proven.)
__device__ __forceinline__ float butterfly8(float wv[8], int lane) {
#pragma unroll
    for (int step = 0; step < 3; step++) {
        const int off = 4 >> step;
        const bool up = (lane & off) != 0;
#pragma unroll
        for (int i = 0; i < 4; i++) {
            if (i < (4 >> step)) {
                const float send = up ? wv[i] : wv[i + (4 >> step)];
                const float recv = __shfl_xor_sync(0xffffffffu, send, off);
                wv[i] = (up ? wv[i + (4 >> step)] : wv[i]) + recv;
            }
        }
    }
    float s = wv[0];
    s += __shfl_xor_sync(0xffffffffu, s, 8);
    s += __shfl_xor_sync(0xffffffffu, s, 16);
    return s;
}

// ---------------------------------------------------------------------------
// Pass 1 = R13/R16-proven hot loop (row-list compaction, q in smem via
// volatile LDS, xv in registers, dual butterfly8, scalar accumulate) + fused
// combine tail (fence+counter last-block election) + a PDL trigger at block
// start so the dependent gemv can launch early and preload W while pass1 runs.
// exp(-1e9)==0 in fp32 => skipping masked rows is exact; |score|<~4 => no
// max subtraction needed.
// ---------------------------------------------------------------------------
__global__ void __launch_bounds__(128, 8)
pool_pass1(const float* __restrict__ x,
           const int* __restrict__ mask,   // bool coerced to int32 by harness
           const float* __restrict__ q)
{
#if __CUDA_ARCH__ >= 900
    if (threadIdx.x == 0) cudaTriggerProgrammaticLaunchCompletion();
#endif

    const int blk  = blockIdx.x;
    const int b    = blk / CHUNKS;
    const int c    = blk % CHUNKS;
    const int w    = threadIdx.x >> 5;
    const int lane = threadIdx.x & 31;

    __shared__ float4 qS[H_][32];           // query chunks, lane-strided
    __shared__ float  sP[WARPS][2][16];     // double-buffered weight broadcast
    __shared__ float  sAcc[WARPS][KD_ * H_];
    __shared__ float  sZ[WARPS][H_];
    __shared__ int    rowsS[WARPS][ROWS_PER_WARP + 4];
    __shared__ bool   isLast;
    __shared__ float  Zs[H_];

    // qS[h][lane] = floats [lane*4, lane*4+4) of head h's query (w == h)
    qS[w][lane] = *reinterpret_cast<const float4*>(q + w * KD_ + lane * 4);

    // ---- build this warp's live-row list (once) ----
    const int l0 = c * (L_ / CHUNKS) + w * ROWS_PER_WARP;
    const int* mb = mask + (size_t)b * L_ + l0;
    int cnt = 0;
#pragma unroll
    for (int half = 0; half < 2; half++) {
        const unsigned mm = __ballot_sync(0xffffffffu, mb[half * 32 + lane] != 0);
        const int rank = __popc(mm & ((1u << lane) - 1));
        if ((mm >> lane) & 1u) rowsS[w][cnt + rank] = half * 32 + lane;
        cnt += __popc(mm);
    }
    if (lane < 4) rowsS[w][cnt + lane] = 0;   // pad (zero-weighted later)
    __syncthreads();                          // qS visible to all warps

    float acc[4][H_];
#pragma unroll
    for (int j = 0; j < 4; j++)
#pragma unroll
        for (int h = 0; h < H_; h++) acc[j][h] = 0.0f;
    float zaccA = 0.0f, zaccB = 0.0f;

    const char* baseL = (const char*)(x + (size_t)b * L_ * KD_ + (size_t)l0 * KD_)
                        + lane * 16;
    const uint32_t qAddr = smem_u32(&qS[0][lane]);   // +512*h per head
    const int myrow = (lane & 7) >> 1;

    int pb = 0;
#pragma unroll 1
    for (int base = 0; base < cnt; base += 4) {
        const float keep = (base + myrow < cnt) ? 1.0f : 0.0f;

        int r[4];
#pragma unroll
        for (int i = 0; i < 4; i++) r[i] = rowsS[w][base + i];   // LDS broadcast

        float4 xv[4];
#pragma unroll
        for (int i = 0; i < 4; i++)
            xv[i] = *reinterpret_cast<const float4*>(baseL + ((unsigned)r[i] << 9));

        // ---- batch A: heads 0,1 -> wv[row*2 + hh] ----
        float wv[8];
        {
            const float4 qa = lds128v(qAddr);
            const float4 qb = lds128v(qAddr + 512);
#pragma unroll
            for (int i = 0; i < 4; i++) {
                wv[i * 2 + 0] = xv[i].x * qa.x + xv[i].y * qa.y
                              + xv[i].z * qa.z + xv[i].w * qa.w;
                wv[i * 2 + 1] = xv[i].x * qb.x + xv[i].y * qb.y
                              + xv[i].z * qb.z + xv[i].w * qb.w;
            }
        }
        float eA = __expf(butterfly8(wv, lane)) * keep;

        // ---- batch B: heads 2,3 ----
        {
            const float4 qc = lds128v(qAddr + 1024);
            const float4 qd = lds128v(qAddr + 1536);
#pragma unroll
            for (int i = 0; i < 4; i++) {
                wv[i * 2 + 0] = xv[i].x * qc.x + xv[i].y * qc.y
                              + xv[i].z * qc.z + xv[i].w * qc.w;
                wv[i * 2 + 1] = xv[i].x * qd.x + xv[i].y * qd.y
                              + xv[i].z * qd.z + xv[i].w * qd.w;
            }
        }
        float eB = __expf(butterfly8(wv, lane)) * keep;

        // ---- broadcast weights: lanes 0..7 carry the distinct values ----
        if (lane < 8) {
            const int row = lane >> 1, hh = lane & 1;
            sP[w][pb][row * 4 + hh]     = eA;   // heads 0,1
            sP[w][pb][row * 4 + 2 + hh] = eB;   // heads 2,3
        } else {
            eA = 0.0f; eB = 0.0f;
        }
        __syncwarp();
        zaccA += eA;                    // Z[lane&1]     partial
        zaccB += eB;                    // Z[2+(lane&1)] partial

        // ---- accumulate 4 rows (xv in registers, scalar FMA) ----
#pragma unroll
        for (int i = 0; i < 4; i++) {
            const float4 pv = *reinterpret_cast<const float4*>(&sP[w][pb][i * 4]);
            acc[0][0] = fmaf(xv[i].x, pv.x, acc[0][0]);
            acc[0][1] = fmaf(xv[i].x, pv.y, acc[0][1]);
            acc[0][2] = fmaf(xv[i].x, pv.z, acc[0][2]);
            acc[0][3] = fmaf(xv[i].x, pv.w, acc[0][3]);
            acc[1][0] = fmaf(xv[i].y, pv.x, acc[1][0]);
            acc[1][1] = fmaf(xv[i].y, pv.y, acc[1][1]);
            acc[1][2] = fmaf(xv[i].y, pv.z, acc[1][2]);
            acc[1][3] = fmaf(xv[i].y, pv.w, acc[1][3]);
            acc[2][0] = fmaf(xv[i].z, pv.x, acc[2][0]);
            acc[2][1] = fmaf(xv[i].z, pv.y, acc[2][1]);
            acc[2][2] = fmaf(xv[i].z, pv.z, acc[2][2]);
            acc[2][3] = fmaf(xv[i].z, pv.w, acc[2][3]);
            acc[3][0] = fmaf(xv[i].w, pv.x, acc[3][0]);
            acc[3][1] = fmaf(xv[i].w, pv.y, acc[3][1]);
            acc[3][2] = fmaf(xv[i].w, pv.z, acc[3][2]);
            acc[3][3] = fmaf(xv[i].w, pv.w, acc[3][3]);
        }
        pb ^= 1;                       // next iter writes other sP buffer; its
                                       // syncwarp fences reuse of this one.
    }

    // Z reduce: same-parity lanes -> lanes 0,1 hold (Z0,Z1) and (Z2,Z3)
    float zA = zaccA, zB = zaccB;
#pragma unroll
    for (int off = 16; off >= 2; off >>= 1) {
        zA += __shfl_xor_sync(0xffffffffu, zA, off);
        zB += __shfl_xor_sync(0xffffffffu, zB, off);
    }

    // ---- block-level deterministic reduce ----
#pragma unroll
    for (int j = 0; j < 4; j++)
#pragma unroll
        for (int h = 0; h < H_; h++)
            sAcc[w][(lane * 4 + j) * H_ + h] = acc[j][h];   // idx = k*H + h
    if (lane < 2) {
        sZ[w][lane]     = zA;
        sZ[w][2 + lane] = zB;
    }
    __syncthreads();

    for (int idx = threadIdx.x; idx < KD_ * H_; idx += 128) {
        float vv = 0.f;
#pragma unroll
        for (int ww = 0; ww < WARPS; ww++) vv += sAcc[ww][idx];
        g_pacc[blk][idx] = vv;
    }
    if (threadIdx.x < H_) {
        float vv = 0.f;
#pragma unroll
        for (int ww = 0; ww < WARPS; ww++) vv += sZ[ww][threadIdx.x];
        g_pZ[blk][threadIdx.x] = vv;
    }

    // ---- fused combine: last block per batch does the chunk reduction ----
    if (threadIdx.x == 0) {
        __threadfence();                         // publish g_pacc/g_pZ writes
        const int t = atomicAdd(&g_cnt[b], 1);
        isLast = (t == CHUNKS - 1);
        if (isLast) g_cnt[b] = 0;                // restore invariant for replay
    }
    __syncthreads();
    if (!isLast) return;

    if (threadIdx.x < H_) {
        float vv = 0.f;
#pragma unroll
        for (int cc = 0; cc < CHUNKS; cc++) vv += g_pZ[b * CHUNKS + cc][threadIdx.x];
        Zs[threadIdx.x] = vv;
    }
    __syncthreads();
#pragma unroll
    for (int e = 0; e < 4; e++) {
        const int idx = threadIdx.x + e * 128;   // coalesced
        float vv = 0.f;
#pragma unroll
        for (int cc = 0; cc < CHUNKS; cc++) vv += g_pacc[b * CHUNKS + cc][idx];
        g_pooled[b][idx] = vv / Zs[idx & (H_ - 1)];
    }
}

// ---------------------------------------------------------------------------
// Pass 2: out = relu(pooled @ W^T + b + relu(emb[num])).
// PDL structure: the PREAMBLE (everything not depending on pass1 — W rows
// into registers, bias, num, emb) runs while pass1 is still executing; then
// cudaGridDependencySynchronize() waits for pass1 completion; the post-sync
// critical path is just 4 g_pooled loads + 64 FMA + warp reduce.
// ---------------------------------------------------------------------------
__global__ void __launch_bounds__(256)
pool_gemv(const float* __restrict__ W,
          const float* __restrict__ bias,
          const float* __restrict__ emb,
          const int* __restrict__ num,
          float* __restrict__ out)
{
    const int b    = blockIdx.x >> 3;
    const int og   = blockIdx.x & 7;
    const int tid  = threadIdx.x;
    const int wrp  = tid >> 5;
    const int lane = tid & 31;
    const int o0   = og * 32 + wrp * 4;

    // ---- preamble: independent of pass1 ----
    float4 wreg[4][4];
#pragma unroll
    for (int j = 0; j < 4; j++)
#pragma unroll
        for (int qi = 0; qi < 4; qi++)
            wreg[j][qi] = *reinterpret_cast<const float4*>(
                W + (size_t)(o0 + j) * (KD_ * H_) + qi * 128 + lane * 4);

    float bj[4], ej[4];
    if (lane == 0) {
        const int nb = num[b];
#pragma unroll
        for (int j = 0; j < 4; j++) {
            bj[j] = bias[o0 + j];
            ej[j] = emb[(size_t)nb * OUT_ + o0 + j];
        }
    }

#if __CUDA_ARCH__ >= 900
    cudaGridDependencySynchronize();   // wait for pass1 (g_pooled valid)
#endif

    // ---- post-sync: pooled loads (L2-broadcast across blocks) + dot ----
    float4 pv[4];
#pragma unroll
    for (int qi = 0; qi < 4; qi++)
        pv[qi] = *reinterpret_cast<const float4*>(
            &g_pooled[b][qi * 128 + lane * 4]);

    float a[4];
#pragma unroll
    for (int j = 0; j < 4; j++) {
        float ssum = 0.f;
#pragma unroll
        for (int qi = 0; qi < 4; qi++)
            ssum = fmaf(wreg[j][qi].x, pv[qi].x, fmaf(wreg[j][qi].y, pv[qi].y,
                   fmaf(wreg[j][qi].z, pv[qi].z, fmaf(wreg[j][qi].w, pv[qi].w, ssum))));
        a[j] = warp_sum32(ssum);
    }

    if (lane == 0) {
#pragma unroll
        for (int j = 0; j < 4; j++) {
            const int o = o0 + j;
            float vv = a[j] + bj[j] + fmaxf(ej[j], 0.f);
            out[(size_t)b * OUT_ + o] = fmaxf(vv, 0.f);
        }
    }
}

// ---------------------------------------------------------------------------
// Launch.  Inputs (metadata order): x, mask, num, queries, W, b, emb
// gemv goes through cudaLaunchKernelEx with the PDL attribute; on any
// failure we fall back to a plain launch (identical semantics — the
// grid-dependency sync is trivially satisfied without PDL).
// ---------------------------------------------------------------------------
extern "C" void kernel_launch(void* const* d_in, const int* in_sizes, int n_in,
                              void* d_out, int out_size)
{
    const float* x    = (const float*)d_in[0];
    const int*   mask = (const int*)d_in[1];     // bool -> int32 on upload
    const int*   num  = (const int*)d_in[2];
    const float* q    = (const float*)d_in[3];
    const float* W    = (const float*)d_in[4];
    const float* bias = (const float*)d_in[5];
    const float* emb  = (const float*)d_in[6];
    float*       out  = (float*)d_out;

    pool_pass1<<<NBLK1, 128>>>(x, mask, q);

    cudaLaunchConfig_t cfg = {};
    cfg.gridDim  = dim3(B_ * 8);
    cfg.blockDim = dim3(256);
    cfg.stream   = 0;
    cudaLaunchAttribute attrs[1];
    attrs[0].id = cudaLaunchAttributeProgrammaticStreamSerialization;
    attrs[0].val.programmaticStreamSerializationAllowed = 1;
    cfg.attrs    = attrs;
    cfg.numAttrs = 1;

    const cudaError_t e =
        cudaLaunchKernelEx(&cfg, pool_gemv, W, bias, emb, num, out);
    if (e != cudaSuccess)
        pool_gemv<<<B_ * 8, 256>>>(W, bias, emb, num, out);
}